// round 16
// baseline (speedup 1.0000x reference)
#include <cuda_runtime.h>
#include <cuda_fp16.h>
#include <math.h>
#include <stdint.h>

#define BB 2
#define SS 2048
#define DD 1024
#define HH 16
#define HD 64
#define MTOT (BB*SS)      // 4096
#define NBH  (BB*HH)      // 32

// ---------------- scratch (device globals) ----------------
__device__ __half g_xh[MTOT*DD];
__device__ __half g_wqh[DD*DD];
__device__ __half g_wkh[DD*DD];
__device__ __half g_wvh[DD*DD];
__device__ __half g_wph[DD*DD];
__device__ __half g_wt[32*DD];       // [32][1024] transposed Wr|Ws|zeros, fp16
__device__ __half g_qh[NBH*SS*HD];
__device__ __half g_kh[NBH*SS*HD];
__device__ __half g_vh[NBH*SS*HD];
__device__ __half g_of[MTOT*DD];     // attention output, fp16 (unscaled)
__device__ float  g_dotp[8*MTOT*24]; // gating partial dots [ky][row][24]

// ---------------- helpers ----------------
__device__ __forceinline__ uint32_t smem_u32(const void* p) {
    return (uint32_t)__cvta_generic_to_shared(p);
}
__device__ __forceinline__ void ldsm4(uint32_t r[4], uint32_t a) {
    asm volatile("ldmatrix.sync.aligned.m8n8.x4.shared.b16 {%0,%1,%2,%3},[%4];"
                 : "=r"(r[0]), "=r"(r[1]), "=r"(r[2]), "=r"(r[3]) : "r"(a));
}
__device__ __forceinline__ void ldsm4t(uint32_t r[4], uint32_t a) {
    asm volatile("ldmatrix.sync.aligned.m8n8.x4.trans.shared.b16 {%0,%1,%2,%3},[%4];"
                 : "=r"(r[0]), "=r"(r[1]), "=r"(r[2]), "=r"(r[3]) : "r"(a));
}
__device__ __forceinline__ void mma16816(float c[4], const uint32_t a[4],
                                         uint32_t b0, uint32_t b1) {
    asm volatile("mma.sync.aligned.m16n8k16.row.col.f32.f16.f16.f32 "
                 "{%0,%1,%2,%3},{%4,%5,%6,%7},{%8,%9},{%0,%1,%2,%3};"
                 : "+f"(c[0]), "+f"(c[1]), "+f"(c[2]), "+f"(c[3])
                 : "r"(a[0]), "r"(a[1]), "r"(a[2]), "r"(a[3]), "r"(b0), "r"(b1));
}
__device__ __forceinline__ void mma16816h(uint32_t c[2], const uint32_t a[4],
                                          uint32_t b0, uint32_t b1) {
    asm volatile("mma.sync.aligned.m16n8k16.row.col.f16.f16.f16.f16 "
                 "{%0,%1},{%2,%3,%4,%5},{%6,%7},{%0,%1};"
                 : "+r"(c[0]), "+r"(c[1])
                 : "r"(a[0]), "r"(a[1]), "r"(a[2]), "r"(a[3]), "r"(b0), "r"(b1));
}
__device__ __forceinline__ uint32_t ex2_f16x2(uint32_t s) {
    uint32_t d;
    asm("ex2.approx.f16x2 %0, %1;" : "=r"(d) : "r"(s));
    return d;
}
#define CP_ASYNC16(dst, src) \
    asm volatile("cp.async.cg.shared.global [%0], [%1], 16;" \
                 :: "r"((uint32_t)(dst)), "l"(src) : "memory")
#define CP_COMMIT() asm volatile("cp.async.commit_group;" ::: "memory")
#define CP_WAIT1()  asm volatile("cp.async.wait_group 1;" ::: "memory")
#define CP_WAIT0()  asm volatile("cp.async.wait_group 0;" ::: "memory")

// ============================================================================
// split inputs. z=0..3: Wq/Wk/Wv/Wp -> fp16. z=4..7: x quarters.
// z=8: transpose Wr|Ws into g_wt[32][1024] fp16 (rows 17..31 zero).
// ============================================================================
__global__ void split_all(const float* __restrict__ x,
                          const float* __restrict__ Wq, const float* __restrict__ Wk,
                          const float* __restrict__ Wv, const float* __restrict__ Wp,
                          const float* __restrict__ Wr, const float* __restrict__ Ws)
{
    const int z = blockIdx.z;
    if (z == 8) {
        int idx = blockIdx.x * 256 + threadIdx.x;
        if (idx < 32 * DD) {
            const int c = idx >> 10, k = idx & (DD - 1);
            float v = 0.0f;
            if (c < 15)      v = Wr[k * 15 + c];
            else if (c < 17) v = Ws[k * 2 + (c - 15)];
            g_wt[c * DD + k] = __float2half_rn(v);
        }
        return;
    }
    const float* src; __half* hi;
    switch (z) {
        case 0: src = Wq; hi = g_wqh; break;
        case 1: src = Wk; hi = g_wkh; break;
        case 2: src = Wv; hi = g_wvh; break;
        case 3: src = Wp; hi = g_wph; break;
        default: {
            int i = (z - 4) * (1024 * 256) + blockIdx.x * 256 + threadIdx.x;
            float4 v = ((const float4*)x)[i];
            __half2* H = (__half2*)g_xh;
            H[2*i]   = __floats2half2_rn(v.x, v.y);
            H[2*i+1] = __floats2half2_rn(v.z, v.w);
            return;
        }
    }
    int i = blockIdx.x * blockDim.x + threadIdx.x;
    float4 v = ((const float4*)src)[i];
    __half2* H = (__half2*)hi;
    H[2*i]   = __floats2half2_rn(v.x, v.y);
    H[2*i+1] = __floats2half2_rn(v.z, v.w);
}

// ============================================================================
// Dense GEMM (pure fp16 HMMA, 1-pass, fp32 accum), BK=64, 3-stage cp.async,
// 2 CTAs/SM. mode 0: QKV (z=blockIdx.z). mode 1: proj (gate scale in
// prologue/epilogue).
// Stage (halfs): A[128][72] @0, B[64][136] @9216. Stage = 35840 B.
// ============================================================================
#define DG_STAGE_B 35840

__device__ __forceinline__ void dg_load_chunk(
    uint32_t st, const __half* Ag, const __half* Bhg, int m0, int n0, int k0, int tid)
{
    #pragma unroll
    for (int sub = 0; sub < 4; sub++) {
        int id = tid + sub * 256;
        int r = id >> 3, j = id & 7;
        CP_ASYNC16(st + (r * 72 + j * 8) * 2, Ag + (size_t)(m0 + r) * DD + k0 + j * 8);
    }
    #pragma unroll
    for (int sub = 0; sub < 4; sub++) {
        int id = tid + sub * 256;
        int r = id >> 4, j = id & 15;
        CP_ASYNC16(st + (9216 + r * 136 + j * 8) * 2,
                   Bhg + (size_t)(k0 + r) * DD + n0 + j * 8);
    }
}

__global__ void __launch_bounds__(256, 2)
dense_gemm(int mode, const float* __restrict__ bq, const float* __restrict__ bk,
           const float* __restrict__ bv, float* __restrict__ outp)
{
    extern __shared__ __half smdyn[];
    __shared__ float s_scale[128];
    const uint32_t sb = smem_u32(smdyn);
    const int tid = threadIdx.x, lane = tid & 31, wid = tid >> 5;
    const int z = (mode == 0) ? blockIdx.z : 3;

    const __half *Ag, *Bhg; const float* bias;
    if (z == 0)      { Ag = g_xh; Bhg = g_wqh; bias = bq; }
    else if (z == 1) { Ag = g_xh; Bhg = g_wkh; bias = bk; }
    else if (z == 2) { Ag = g_xh; Bhg = g_wvh; bias = bv; }
    else             { Ag = g_of; Bhg = g_wph; bias = bq; }

    const int m0 = blockIdx.y * 128, n0 = blockIdx.x * 128;
    const int wm = (wid >> 2) * 64, wn = (wid & 3) * 32;

    float c[4][4][4];
    #pragma unroll
    for (int i = 0; i < 4; i++)
        #pragma unroll
        for (int j = 0; j < 4; j++)
            #pragma unroll
            for (int q = 0; q < 4; q++) c[i][j][q] = 0.0f;

    dg_load_chunk(sb,              Ag, Bhg, m0, n0, 0,  tid); CP_COMMIT();
    dg_load_chunk(sb + DG_STAGE_B, Ag, Bhg, m0, n0, 64, tid); CP_COMMIT();

    // mode 1: compute per-row gate scales from partial dots (hidden under loads)
    if (mode == 1 && tid < 128) {
        const int row = m0 + tid;
        float dt[17];
        #pragma unroll
        for (int i = 0; i < 17; i++)
            dt[i] = (i < 15) ? bk[i] : bv[i - 15];     // br | bs
        #pragma unroll
        for (int ky = 0; ky < 8; ky++) {
            const float* pp = &g_dotp[((size_t)ky * MTOT + row) * 24];
            #pragma unroll
            for (int i = 0; i < 17; i++) dt[i] += pp[i];
        }
        float mx = -1e30f;
        #pragma unroll
        for (int i = 0; i < 15; i++) mx = fmaxf(mx, dt[i]);
        float g[15]; float sum = 0.0f;
        #pragma unroll
        for (int i = 0; i < 15; i++) { g[i] = expf(dt[i] - mx); sum += g[i]; }
        const float inv = 1.0f / sum;
        float a = -1e30f, b2 = -1e30f, c2 = -1e30f;
        #pragma unroll
        for (int i = 0; i < 15; i++) {
            const float v = g[i] * inv;
            if (v > a)       { c2 = b2; b2 = a; a = v; }
            else if (v > b2) { c2 = b2; b2 = v; }
            else if (v > c2) { c2 = v; }
        }
        const float top3 = a + b2 + c2;
        const float m2 = fmaxf(dt[15], dt[16]);
        const float e0 = expf(dt[15] - m2), e1 = expf(dt[16] - m2);
        const float sw0 = e0 / (e0 + e1), sw1 = e1 / (e0 + e1);
        s_scale[tid] = 2.0f * sw0 + 6.0f * sw1 * top3;
    }

    for (int ch = 0; ch < 16; ch++) {
        CP_WAIT1();
        __syncthreads();
        if (ch + 2 < 16)
            dg_load_chunk(sb + ((ch + 2) % 3) * DG_STAGE_B, Ag, Bhg,
                          m0, n0, (ch + 2) * 64, tid);
        CP_COMMIT();

        const uint32_t stA = sb + (ch % 3) * DG_STAGE_B;
        const uint32_t stB = stA + 18432;

        #pragma unroll
        for (int kk = 0; kk < 4; kk++) {
            uint32_t ah[4][4];
            #pragma unroll
            for (int mi = 0; mi < 4; mi++) {
                const uint32_t ro = (wm + mi * 16 + (lane & 15)) * 72
                                  + kk * 16 + (lane >> 4) * 8;
                ldsm4(ah[mi], stA + ro * 2);
            }
            #pragma unroll
            for (int p = 0; p < 2; p++) {
                const uint32_t ro = (kk * 16 + (lane & 15)) * 136
                                  + wn + p * 16 + (lane >> 4) * 8;
                uint32_t bh[4];
                ldsm4t(bh, stB + ro * 2);
                #pragma unroll
                for (int mi = 0; mi < 4; mi++) {
                    mma16816(c[mi][2*p],   ah[mi], bh[0], bh[1]);
                    mma16816(c[mi][2*p+1], ah[mi], bh[2], bh[3]);
                }
            }
        }
    }

    if (mode == 1) {
        #pragma unroll
        for (int mi = 0; mi < 4; mi++) {
            const int lm = wm + mi * 16 + (lane >> 2);
            const int mBase = m0 + lm;
            const float s0v = s_scale[lm];
            const float s1v = s_scale[lm + 8];
            #pragma unroll
            for (int ni = 0; ni < 4; ni++) {
                const int n = n0 + wn + ni * 8 + (lane & 3) * 2;
                const float b0v = bias[n], b1v = bias[n + 1];
                *(float2*)&outp[(size_t)mBase * DD + n] =
                    make_float2(c[mi][ni][0] * s0v + b0v, c[mi][ni][1] * s0v + b1v);
                *(float2*)&outp[(size_t)(mBase + 8) * DD + n] =
                    make_float2(c[mi][ni][2] * s1v + b0v, c[mi][ni][3] * s1v + b1v);
            }
        }
    } else {
        __half* dst = (z == 0) ? g_qh : (z == 1) ? g_kh : g_vh;
        #pragma unroll
        for (int mi = 0; mi < 4; mi++) {
            #pragma unroll
            for (int ni = 0; ni < 4; ni++) {
                const int n = n0 + wn + ni * 8 + (lane & 3) * 2;
                const int h = n >> 6, d = n & 63;
                const float b0v = bias[n], b1v = bias[n + 1];
                #pragma unroll
                for (int hf = 0; hf < 2; hf++) {
                    const int m = m0 + wm + mi * 16 + (lane >> 2) + hf * 8;
                    const int b = m >> 11, sI = m & (SS - 1);
                    const size_t idx = (((size_t)(b * HH + h)) * SS + sI) * HD + d;
                    *(__half2*)&dst[idx] =
                        __floats2half2_rn(c[mi][ni][hf*2 + 0] + b0v,
                                          c[mi][ni][hf*2 + 1] + b1v);
                }
            }
        }
    }
}

// ============================================================================
// Fused flash attention (fp16-acc QK, ex2.f16x2 softmax, fp32-acc PV,
// BN=128, 2-stage cp.async distance-1, 2 CTAs/SM). UNCHANGED from R15.
// ============================================================================
#define AT_STAGE_B 36864

__device__ __forceinline__ void at_load_kv(
    uint32_t st, const __half* Kh, const __half* Vh, int kt, int tid)
{
    #pragma unroll
    for (int sub = 0; sub < 4; sub++) {
        int id = tid + sub * 256;
        int r = id >> 3, j = id & 7;
        CP_ASYNC16(st + (r * 72 + j * 8) * 2,         Kh + (size_t)(kt + r) * HD + j * 8);
        CP_ASYNC16(st + (9216 + r * 72 + j * 8) * 2,  Vh + (size_t)(kt + r) * HD + j * 8);
    }
}

__global__ void __launch_bounds__(256, 2)
attn(const float* __restrict__ temp, const float* __restrict__ qe)
{
    extern __shared__ __half smdyn[];
    const uint32_t sb = smem_u32(smdyn);

    const int bh = blockIdx.y;
    const int m0 = blockIdx.x * 128;
    const size_t hb = (size_t)bh * SS * HD;
    const __half* Khp = g_kh + hb;
    const __half* Vhp = g_vh + hb;
    const int h = bh & (HH - 1);

    const int tid = threadIdx.x, lane = tid & 31, wid = tid >> 5;
    const int wm = wid * 16;

    uint32_t qa_h[4][4];
    {
        __half* Qs = smdyn;
        const float sc = log1pf(expf(temp[h])) * 0.125f * 1.44269504f;
        #pragma unroll
        for (int it = 0; it < 4; it++) {
            int cid = tid + it * 256;
            int r = cid >> 3, j = cid & 7;
            uint4 raw = *(const uint4*)&g_qh[hb + (size_t)(m0 + r) * HD + j * 8];
            __half2* hp = (__half2*)&raw;
            float2 f[4];
            float ss = 0.0f;
            #pragma unroll
            for (int t = 0; t < 4; t++) {
                f[t] = __half22float2(hp[t]);
                ss += f[t].x * f[t].x + f[t].y * f[t].y;
            }
            ss += __shfl_xor_sync(0xffffffffu, ss, 1);
            ss += __shfl_xor_sync(0xffffffffu, ss, 2);
            ss += __shfl_xor_sync(0xffffffffu, ss, 4);
            const float rn = rsqrtf(ss + 1e-12f);
            __half2 oh4[4];
            #pragma unroll
            for (int t = 0; t < 4; t++) {
                const int d = j * 8 + 2 * t;
                oh4[t] = __floats2half2_rn((f[t].x * rn + qe[h * HD + d])     * sc,
                                           (f[t].y * rn + qe[h * HD + d + 1]) * sc);
            }
            *(uint4*)&Qs[r * 72 + j * 8] = *(uint4*)oh4;
        }
        __syncthreads();
        #pragma unroll
        for (int kk = 0; kk < 4; kk++)
            ldsm4(qa_h[kk], sb + ((wm + (lane & 15)) * 72 + kk*16 + (lane >> 4)*8) * 2);
        __syncthreads();
    }

    float ol0 = 0.0f, ol1 = 0.0f;
    float oacc[8][4];
    #pragma unroll
    for (int i = 0; i < 8; i++)
        #pragma unroll
        for (int j = 0; j < 4; j++) oacc[i][j] = 0.0f;

    at_load_kv(sb, Khp, Vhp, 0, tid); CP_COMMIT();

    for (int it16 = 0; it16 < SS / 128; it16++) {
        CP_WAIT0();
        __syncthreads();
        if (it16 + 1 < SS / 128) {
            at_load_kv(sb + ((it16 + 1) & 1) * AT_STAGE_B, Khp, Vhp, (it16 + 1) * 128, tid);
            CP_COMMIT();
        }

        const uint32_t stK = sb + (it16 & 1) * AT_STAGE_B;
        const uint32_t stV = stK + 18432;

        uint32_t sc16[16][2];
        #pragma unroll
        for (int i = 0; i < 16; i++) { sc16[i][0] = 0u; sc16[i][1] = 0u; }

        #pragma unroll
        for (int kk = 0; kk < 4; kk++) {
            #pragma unroll
            for (int p = 0; p < 8; p++) {
                const uint32_t ro = (p*16 + (lane & 7) + ((lane >> 4) << 3)) * 72
                                  + kk*16 + ((lane >> 3) & 1) * 8;
                uint32_t rh[4];
                ldsm4(rh, stK + ro * 2);
                mma16816h(sc16[2*p],   qa_h[kk], rh[0], rh[1]);
                mma16816h(sc16[2*p+1], qa_h[kk], rh[2], rh[3]);
            }
        }

        uint32_t pa[8][4];
        __half2 acc0 = __floats2half2_rn(0.f, 0.f);
        __half2 acc1 = acc0;
        #pragma unroll
        for (int j = 0; j < 16; j++) {
            uint32_t e0 = ex2_f16x2(sc16[j][0]);
            uint32_t e1 = ex2_f16x2(sc16[j][1]);
            pa[j >> 1][(j & 1) * 2 + 0] = e0;
            pa[j >> 1][(j & 1) * 2 + 1] = e1;
            acc0 = __hadd2(acc0, *(__half2*)&e0);
            acc1 = __hadd2(acc1, *(__half2*)&e1);
        }
        {
            float2 f0 = __half22float2(acc0);
            float2 f1 = __half22float2(acc1);
            ol0 += f0.x + f0.y;
            ol1 += f1.x + f1.y;
        }

        #pragma unroll
        for (int kk2 = 0; kk2 < 8; kk2++) {
            #pragma unroll
            for (int p = 0; p < 4; p++) {
                const uint32_t ro = (kk2*16 + (lane & 7) + ((lane >> 3) & 1) * 8) * 72
                                  + p*16 + (lane >> 4) * 8;
                uint32_t rh[4];
                ldsm4t(rh, stV + ro * 2);
                mma16816(oacc[2*p],   pa[kk2], rh[0], rh[1]);
                mma16816(oacc[2*p+1], pa[kk2], rh[2], rh[3]);
            }
        }
    }

    ol0 += __shfl_xor_sync(0xffffffffu, ol0, 1);
    ol0 += __shfl_xor_sync(0xffffffffu, ol0, 2);
    ol1 += __shfl_xor_sync(0xffffffffu, ol1, 1);
    ol1 += __shfl_xor_sync(0xffffffffu, ol1, 2);

    const int b = bh >> 4;
    const float inv0 = 1.0f / ol0, inv1 = 1.0f / ol1;
    const int s0 = m0 + wm + (lane >> 2);
    #pragma unroll
    for (int di = 0; di < 8; di++) {
        const int d = di * 8 + (lane & 3) * 2;
        *(__half2*)&g_of[((size_t)(b * SS + s0)) * DD + h * HD + d] =
            __floats2half2_rn(oacc[di][0] * inv0, oacc[di][1] * inv0);
        *(__half2*)&g_of[((size_t)(b * SS + s0 + 8)) * DD + h * HD + d] =
            __floats2half2_rn(oacc[di][2] * inv1, oacc[di][3] * inv1);
    }
}

// ============================================================================
// Gating partial dots via HMMA, K-split 8-way: grid (32 m-tiles, 8 k-slices).
// Each CTA: 2 chunks of 64 K, writes fp32 partials to g_dotp[ky][row][24].
// 2-stage cp.async distance-1. Stage: A[128][72] + B[32][72] = 23040 B.
// ============================================================================
#define GT_STAGE_B 23040

__device__ __forceinline__ void gt_load_chunk(uint32_t st, int m0, int k0, int tid)
{
    #pragma unroll
    for (int sub = 0; sub < 4; sub++) {
        int id = tid + sub * 256;
        int r = id >> 3, j = id & 7;
        CP_ASYNC16(st + (r * 72 + j * 8) * 2, g_of + (size_t)(m0 + r) * DD + k0 + j * 8);
    }
    {
        int r = tid >> 3, j = tid & 7;
        CP_ASYNC16(st + (9216 + r * 72 + j * 8) * 2, g_wt + (size_t)r * DD + k0 + j * 8);
    }
}

__global__ void __launch_bounds__(256)
gating_part()
{
    extern __shared__ __half smdyn[];
    const uint32_t sb = smem_u32(smdyn);
    const int tid = threadIdx.x, lane = tid & 31, wid = tid >> 5;
    const int m0 = blockIdx.x * 128;
    const int ky = blockIdx.y;
    const int kb = ky * 128;
    const int wm = wid * 16;

    float c[3][4];
    #pragma unroll
    for (int i = 0; i < 3; i++)
        #pragma unroll
        for (int q = 0; q < 4; q++) c[i][q] = 0.0f;

    gt_load_chunk(sb, m0, kb, tid); CP_COMMIT();

    #pragma unroll
    for (int ch = 0; ch < 2; ch++) {
        CP_WAIT0();
        __syncthreads();
        if (ch + 1 < 2) {
            gt_load_chunk(sb + GT_STAGE_B, m0, kb + 64, tid);
            CP_COMMIT();
        }

        const uint32_t stA = sb + (ch & 1) * GT_STAGE_B;
        const uint32_t stB = stA + 18432;

        #pragma unroll
        for (int kk = 0; kk < 4; kk++) {
            uint32_t a4[4];
            ldsm4(a4, stA + ((wm + (lane & 15)) * 72 + kk * 16 + (lane >> 4) * 8) * 2);
            uint32_t b0[4];
            ldsm4(b0, stB + (((lane & 7) + ((lane >> 4) << 3)) * 72
                             + kk * 16 + ((lane >> 3) & 1) * 8) * 2);
            mma16816(c[0], a4, b0[0], b0[1]);
            mma16816(c[1], a4, b0[2], b0[3]);
            uint32_t b1[4];
            ldsm4(b1, stB + ((16 + (lane & 7) + ((lane >> 4) << 3)) * 72
                             + kk * 16 + ((lane >> 3) & 1) * 8) * 2);
            mma16816(c[2], a4, b1[0], b1[1]);
        }
    }

    #pragma unroll
    for (int ni = 0; ni < 3; ni++) {
        const int col = ni * 8 + (lane & 3) * 2;
        #pragma unroll
        for (int hf = 0; hf < 2; hf++) {
            const int row = m0 + wm + (lane >> 2) + hf * 8;
            float* dst = &g_dotp[((size_t)ky * MTOT + row) * 24 + col];
            dst[0] = c[ni][hf * 2 + 0];
            dst[1] = c[ni][hf * 2 + 1];
        }
    }
}

// ============================================================================
extern "C" void kernel_launch(void* const* d_in, const int* in_sizes, int n_in,
                              void* d_out, int out_size)
{
    const float* x     = (const float*)d_in[0];
    const float* Wq    = (const float*)d_in[1];
    const float* bq    = (const float*)d_in[2];
    const float* Wk    = (const float*)d_in[3];
    const float* bk    = (const float*)d_in[4];
    const float* Wv    = (const float*)d_in[5];
    const float* bv    = (const float*)d_in[6];
    const float* Wp    = (const float*)d_in[7];
    const float* bp    = (const float*)d_in[8];
    const float* Wr    = (const float*)d_in[9];
    const float* br    = (const float*)d_in[10];
    const float* Ws    = (const float*)d_in[11];
    const float* bs    = (const float*)d_in[12];
    const float* temp  = (const float*)d_in[13];
    const float* qe    = (const float*)d_in[14];
    float* out = (float*)d_out;

    static int attr_set = 0;
    if (!attr_set) {
        cudaFuncSetAttribute(dense_gemm, cudaFuncAttributeMaxDynamicSharedMemorySize,
                             3 * DG_STAGE_B);
        cudaFuncSetAttribute(attn, cudaFuncAttributeMaxDynamicSharedMemorySize,
                             2 * AT_STAGE_B);
        cudaFuncSetAttribute(gating_part, cudaFuncAttributeMaxDynamicSharedMemorySize,
                             2 * GT_STAGE_B);
        attr_set = 1;
    }

    split_all<<<dim3(1024, 1, 9), 256>>>(x, Wq, Wk, Wv, Wp, Wr, Ws);

    dense_gemm<<<dim3(8, 32, 3), 256, 3 * DG_STAGE_B>>>(0, bq, bk, bv, nullptr);
    attn<<<dim3(16, 32), 256, 2 * AT_STAGE_B>>>(temp, qe);
    gating_part<<<dim3(32, 8), 256, 2 * GT_STAGE_B>>>();
    dense_gemm<<<dim3(8, 32, 1), 256, 3 * DG_STAGE_B>>>(1, bp, br, bs, out);
}

// round 17
// speedup vs baseline: 1.0130x; 1.0130x over previous
#include <cuda_runtime.h>
#include <cuda_fp16.h>
#include <math.h>
#include <stdint.h>

#define BB 2
#define SS 2048
#define DD 1024
#define HH 16
#define HD 64
#define MTOT (BB*SS)      // 4096
#define NBH  (BB*HH)      // 32

// ---------------- scratch (device globals) ----------------
__device__ __half g_xh[MTOT*DD];
__device__ __half g_wqh[DD*DD];
__device__ __half g_wkh[DD*DD];
__device__ __half g_wvh[DD*DD];
__device__ __half g_wph[DD*DD];
__device__ __half g_wt[32*DD];       // [32][1024] transposed Wr|Ws|zeros, fp16
__device__ __half g_qh[NBH*SS*HD];
__device__ __half g_kh[NBH*SS*HD];
__device__ __half g_vh[NBH*SS*HD];
__device__ __half g_of[MTOT*DD];     // attention output, fp16 (unscaled)
__device__ float  g_dotp[8*MTOT*24]; // gating partial dots [ky][row][24]

// ---------------- helpers ----------------
__device__ __forceinline__ uint32_t smem_u32(const void* p) {
    return (uint32_t)__cvta_generic_to_shared(p);
}
__device__ __forceinline__ void ldsm4(uint32_t r[4], uint32_t a) {
    asm volatile("ldmatrix.sync.aligned.m8n8.x4.shared.b16 {%0,%1,%2,%3},[%4];"
                 : "=r"(r[0]), "=r"(r[1]), "=r"(r[2]), "=r"(r[3]) : "r"(a));
}
__device__ __forceinline__ void ldsm4t(uint32_t r[4], uint32_t a) {
    asm volatile("ldmatrix.sync.aligned.m8n8.x4.trans.shared.b16 {%0,%1,%2,%3},[%4];"
                 : "=r"(r[0]), "=r"(r[1]), "=r"(r[2]), "=r"(r[3]) : "r"(a));
}
__device__ __forceinline__ void mma16816(float c[4], const uint32_t a[4],
                                         uint32_t b0, uint32_t b1) {
    asm volatile("mma.sync.aligned.m16n8k16.row.col.f32.f16.f16.f32 "
                 "{%0,%1,%2,%3},{%4,%5,%6,%7},{%8,%9},{%0,%1,%2,%3};"
                 : "+f"(c[0]), "+f"(c[1]), "+f"(c[2]), "+f"(c[3])
                 : "r"(a[0]), "r"(a[1]), "r"(a[2]), "r"(a[3]), "r"(b0), "r"(b1));
}
__device__ __forceinline__ void mma16816h(uint32_t c[2], const uint32_t a[4],
                                          uint32_t b0, uint32_t b1) {
    asm volatile("mma.sync.aligned.m16n8k16.row.col.f16.f16.f16.f16 "
                 "{%0,%1},{%2,%3,%4,%5},{%6,%7},{%0,%1};"
                 : "+r"(c[0]), "+r"(c[1])
                 : "r"(a[0]), "r"(a[1]), "r"(a[2]), "r"(a[3]), "r"(b0), "r"(b1));
}
__device__ __forceinline__ uint32_t ex2_f16x2(uint32_t s) {
    uint32_t d;
    asm("ex2.approx.f16x2 %0, %1;" : "=r"(d) : "r"(s));
    return d;
}
#define CP_ASYNC16(dst, src) \
    asm volatile("cp.async.cg.shared.global [%0], [%1], 16;" \
                 :: "r"((uint32_t)(dst)), "l"(src) : "memory")
#define CP_COMMIT() asm volatile("cp.async.commit_group;" ::: "memory")
#define CP_WAIT1()  asm volatile("cp.async.wait_group 1;" ::: "memory")
#define CP_WAIT0()  asm volatile("cp.async.wait_group 0;" ::: "memory")

// ============================================================================
// split inputs. z=0..3: Wq/Wk/Wv/Wp -> fp16. z=4..7: x quarters.
// z=8: transpose Wr|Ws into g_wt[32][1024] fp16 (rows 17..31 zero).
// ============================================================================
__global__ void split_all(const float* __restrict__ x,
                          const float* __restrict__ Wq, const float* __restrict__ Wk,
                          const float* __restrict__ Wv, const float* __restrict__ Wp,
                          const float* __restrict__ Wr, const float* __restrict__ Ws)
{
    const int z = blockIdx.z;
    if (z == 8) {
        int idx = blockIdx.x * 256 + threadIdx.x;
        if (idx < 32 * DD) {
            const int c = idx >> 10, k = idx & (DD - 1);
            float v = 0.0f;
            if (c < 15)      v = Wr[k * 15 + c];
            else if (c < 17) v = Ws[k * 2 + (c - 15)];
            g_wt[c * DD + k] = __float2half_rn(v);
        }
        return;
    }
    const float* src; __half* hi;
    switch (z) {
        case 0: src = Wq; hi = g_wqh; break;
        case 1: src = Wk; hi = g_wkh; break;
        case 2: src = Wv; hi = g_wvh; break;
        case 3: src = Wp; hi = g_wph; break;
        default: {
            int i = (z - 4) * (1024 * 256) + blockIdx.x * 256 + threadIdx.x;
            float4 v = ((const float4*)x)[i];
            __half2* H = (__half2*)g_xh;
            H[2*i]   = __floats2half2_rn(v.x, v.y);
            H[2*i+1] = __floats2half2_rn(v.z, v.w);
            return;
        }
    }
    int i = blockIdx.x * blockDim.x + threadIdx.x;
    float4 v = ((const float4*)src)[i];
    __half2* H = (__half2*)hi;
    H[2*i]   = __floats2half2_rn(v.x, v.y);
    H[2*i+1] = __floats2half2_rn(v.z, v.w);
}

// ============================================================================
// Dense GEMM (pure fp16 HMMA, 1-pass, fp32 accum), BK=32, 3-stage cp.async,
// 2 CTAs/SM. (Reverted to R15 config — BK=64 measured slower in R16.)
// mode 0: QKV (z=blockIdx.z). mode 1: proj (gate scale in prologue/epilogue).
// Stage (halfs): Ah[128][40] @0, Bh[32][136] @5120. 18944 B/stage.
// ============================================================================
#define DG_STAGE_B 18944

__device__ __forceinline__ void dg_load_chunk(
    uint32_t st, const __half* Ag, const __half* Bhg, int m0, int n0, int k0, int tid)
{
    #pragma unroll
    for (int sub = 0; sub < 2; sub++) {
        int id = tid + sub * 256;
        int r = id >> 2, j = id & 3;
        CP_ASYNC16(st + (r * 40 + j * 8) * 2, Ag + (size_t)(m0 + r) * DD + k0 + j * 8);
    }
    #pragma unroll
    for (int sub = 0; sub < 2; sub++) {
        int id = tid + sub * 256;
        int r = id >> 4, j = id & 15;
        CP_ASYNC16(st + (5120 + r * 136 + j * 8) * 2,
                   Bhg + (size_t)(k0 + r) * DD + n0 + j * 8);
    }
}

__global__ void __launch_bounds__(256, 2)
dense_gemm(int mode, const float* __restrict__ bq, const float* __restrict__ bk,
           const float* __restrict__ bv, float* __restrict__ outp)
{
    extern __shared__ __half smdyn[];
    __shared__ float s_scale[128];
    const uint32_t sb = smem_u32(smdyn);
    const int tid = threadIdx.x, lane = tid & 31, wid = tid >> 5;
    const int z = (mode == 0) ? blockIdx.z : 3;

    const __half *Ag, *Bhg; const float* bias;
    if (z == 0)      { Ag = g_xh; Bhg = g_wqh; bias = bq; }
    else if (z == 1) { Ag = g_xh; Bhg = g_wkh; bias = bk; }
    else if (z == 2) { Ag = g_xh; Bhg = g_wvh; bias = bv; }
    else             { Ag = g_of; Bhg = g_wph; bias = bq; }

    const int m0 = blockIdx.y * 128, n0 = blockIdx.x * 128;
    const int wm = (wid >> 2) * 64, wn = (wid & 3) * 32;

    float c[4][4][4];
    #pragma unroll
    for (int i = 0; i < 4; i++)
        #pragma unroll
        for (int j = 0; j < 4; j++)
            #pragma unroll
            for (int q = 0; q < 4; q++) c[i][j][q] = 0.0f;

    dg_load_chunk(sb,              Ag, Bhg, m0, n0, 0,  tid); CP_COMMIT();
    dg_load_chunk(sb + DG_STAGE_B, Ag, Bhg, m0, n0, 32, tid); CP_COMMIT();

    // mode 1: per-row gate scales from 8 partial dots (hidden under loads)
    if (mode == 1 && tid < 128) {
        const int row = m0 + tid;
        float dt[17];
        #pragma unroll
        for (int i = 0; i < 17; i++)
            dt[i] = (i < 15) ? bk[i] : bv[i - 15];     // br | bs
        #pragma unroll
        for (int ky = 0; ky < 8; ky++) {
            const float* pp = &g_dotp[((size_t)ky * MTOT + row) * 24];
            #pragma unroll
            for (int i = 0; i < 17; i++) dt[i] += pp[i];
        }
        float mx = -1e30f;
        #pragma unroll
        for (int i = 0; i < 15; i++) mx = fmaxf(mx, dt[i]);
        float g[15]; float sum = 0.0f;
        #pragma unroll
        for (int i = 0; i < 15; i++) { g[i] = expf(dt[i] - mx); sum += g[i]; }
        const float inv = 1.0f / sum;
        float a = -1e30f, b2 = -1e30f, c2 = -1e30f;
        #pragma unroll
        for (int i = 0; i < 15; i++) {
            const float v = g[i] * inv;
            if (v > a)       { c2 = b2; b2 = a; a = v; }
            else if (v > b2) { c2 = b2; b2 = v; }
            else if (v > c2) { c2 = v; }
        }
        const float top3 = a + b2 + c2;
        const float m2 = fmaxf(dt[15], dt[16]);
        const float e0 = expf(dt[15] - m2), e1 = expf(dt[16] - m2);
        const float sw0 = e0 / (e0 + e1), sw1 = e1 / (e0 + e1);
        s_scale[tid] = 2.0f * sw0 + 6.0f * sw1 * top3;
    }

    for (int ch = 0; ch < 32; ch++) {
        CP_WAIT1();
        __syncthreads();
        if (ch + 2 < 32)
            dg_load_chunk(sb + ((ch + 2) % 3) * DG_STAGE_B, Ag, Bhg,
                          m0, n0, (ch + 2) * 32, tid);
        CP_COMMIT();

        const uint32_t stA  = sb + (ch % 3) * DG_STAGE_B;
        const uint32_t stBh = stA + 10240;

        #pragma unroll
        for (int kk = 0; kk < 2; kk++) {
            uint32_t ah[4][4];
            #pragma unroll
            for (int mi = 0; mi < 4; mi++) {
                const uint32_t ro = (wm + mi * 16 + (lane & 15)) * 40
                                  + kk * 16 + (lane >> 4) * 8;
                ldsm4(ah[mi], stA + ro * 2);
            }
            #pragma unroll
            for (int p = 0; p < 2; p++) {
                const uint32_t ro = (kk * 16 + (lane & 15)) * 136
                                  + wn + p * 16 + (lane >> 4) * 8;
                uint32_t bh[4];
                ldsm4t(bh, stBh + ro * 2);
                #pragma unroll
                for (int mi = 0; mi < 4; mi++) {
                    mma16816(c[mi][2*p],   ah[mi], bh[0], bh[1]);
                    mma16816(c[mi][2*p+1], ah[mi], bh[2], bh[3]);
                }
            }
        }
    }

    if (mode == 1) {
        #pragma unroll
        for (int mi = 0; mi < 4; mi++) {
            const int lm = wm + mi * 16 + (lane >> 2);
            const int mBase = m0 + lm;
            const float s0v = s_scale[lm];
            const float s1v = s_scale[lm + 8];
            #pragma unroll
            for (int ni = 0; ni < 4; ni++) {
                const int n = n0 + wn + ni * 8 + (lane & 3) * 2;
                const float b0v = bias[n], b1v = bias[n + 1];
                *(float2*)&outp[(size_t)mBase * DD + n] =
                    make_float2(c[mi][ni][0] * s0v + b0v, c[mi][ni][1] * s0v + b1v);
                *(float2*)&outp[(size_t)(mBase + 8) * DD + n] =
                    make_float2(c[mi][ni][2] * s1v + b0v, c[mi][ni][3] * s1v + b1v);
            }
        }
    } else {
        __half* dst = (z == 0) ? g_qh : (z == 1) ? g_kh : g_vh;
        #pragma unroll
        for (int mi = 0; mi < 4; mi++) {
            #pragma unroll
            for (int ni = 0; ni < 4; ni++) {
                const int n = n0 + wn + ni * 8 + (lane & 3) * 2;
                const int h = n >> 6, d = n & 63;
                const float b0v = bias[n], b1v = bias[n + 1];
                #pragma unroll
                for (int hf = 0; hf < 2; hf++) {
                    const int m = m0 + wm + mi * 16 + (lane >> 2) + hf * 8;
                    const int b = m >> 11, sI = m & (SS - 1);
                    const size_t idx = (((size_t)(b * HH + h)) * SS + sI) * HD + d;
                    *(__half2*)&dst[idx] =
                        __floats2half2_rn(c[mi][ni][hf*2 + 0] + b0v,
                                          c[mi][ni][hf*2 + 1] + b1v);
                }
            }
        }
    }
}

// ============================================================================
// Fused flash attention (fp16-acc QK, ex2.f16x2 softmax, fp32-acc PV,
// BN=128, 2-stage cp.async distance-1, 2 CTAs/SM). UNCHANGED.
// ============================================================================
#define AT_STAGE_B 36864

__device__ __forceinline__ void at_load_kv(
    uint32_t st, const __half* Kh, const __half* Vh, int kt, int tid)
{
    #pragma unroll
    for (int sub = 0; sub < 4; sub++) {
        int id = tid + sub * 256;
        int r = id >> 3, j = id & 7;
        CP_ASYNC16(st + (r * 72 + j * 8) * 2,         Kh + (size_t)(kt + r) * HD + j * 8);
        CP_ASYNC16(st + (9216 + r * 72 + j * 8) * 2,  Vh + (size_t)(kt + r) * HD + j * 8);
    }
}

__global__ void __launch_bounds__(256, 2)
attn(const float* __restrict__ temp, const float* __restrict__ qe)
{
    extern __shared__ __half smdyn[];
    const uint32_t sb = smem_u32(smdyn);

    const int bh = blockIdx.y;
    const int m0 = blockIdx.x * 128;
    const size_t hb = (size_t)bh * SS * HD;
    const __half* Khp = g_kh + hb;
    const __half* Vhp = g_vh + hb;
    const int h = bh & (HH - 1);

    const int tid = threadIdx.x, lane = tid & 31, wid = tid >> 5;
    const int wm = wid * 16;

    uint32_t qa_h[4][4];
    {
        __half* Qs = smdyn;
        const float sc = log1pf(expf(temp[h])) * 0.125f * 1.44269504f;
        #pragma unroll
        for (int it = 0; it < 4; it++) {
            int cid = tid + it * 256;
            int r = cid >> 3, j = cid & 7;
            uint4 raw = *(const uint4*)&g_qh[hb + (size_t)(m0 + r) * HD + j * 8];
            __half2* hp = (__half2*)&raw;
            float2 f[4];
            float ss = 0.0f;
            #pragma unroll
            for (int t = 0; t < 4; t++) {
                f[t] = __half22float2(hp[t]);
                ss += f[t].x * f[t].x + f[t].y * f[t].y;
            }
            ss += __shfl_xor_sync(0xffffffffu, ss, 1);
            ss += __shfl_xor_sync(0xffffffffu, ss, 2);
            ss += __shfl_xor_sync(0xffffffffu, ss, 4);
            const float rn = rsqrtf(ss + 1e-12f);
            __half2 oh4[4];
            #pragma unroll
            for (int t = 0; t < 4; t++) {
                const int d = j * 8 + 2 * t;
                oh4[t] = __floats2half2_rn((f[t].x * rn + qe[h * HD + d])     * sc,
                                           (f[t].y * rn + qe[h * HD + d + 1]) * sc);
            }
            *(uint4*)&Qs[r * 72 + j * 8] = *(uint4*)oh4;
        }
        __syncthreads();
        #pragma unroll
        for (int kk = 0; kk < 4; kk++)
            ldsm4(qa_h[kk], sb + ((wm + (lane & 15)) * 72 + kk*16 + (lane >> 4)*8) * 2);
        __syncthreads();
    }

    float ol0 = 0.0f, ol1 = 0.0f;
    float oacc[8][4];
    #pragma unroll
    for (int i = 0; i < 8; i++)
        #pragma unroll
        for (int j = 0; j < 4; j++) oacc[i][j] = 0.0f;

    at_load_kv(sb, Khp, Vhp, 0, tid); CP_COMMIT();

    for (int it16 = 0; it16 < SS / 128; it16++) {
        CP_WAIT0();
        __syncthreads();
        if (it16 + 1 < SS / 128) {
            at_load_kv(sb + ((it16 + 1) & 1) * AT_STAGE_B, Khp, Vhp, (it16 + 1) * 128, tid);
            CP_COMMIT();
        }

        const uint32_t stK = sb + (it16 & 1) * AT_STAGE_B;
        const uint32_t stV = stK + 18432;

        uint32_t sc16[16][2];
        #pragma unroll
        for (int i = 0; i < 16; i++) { sc16[i][0] = 0u; sc16[i][1] = 0u; }

        #pragma unroll
        for (int kk = 0; kk < 4; kk++) {
            #pragma unroll
            for (int p = 0; p < 8; p++) {
                const uint32_t ro = (p*16 + (lane & 7) + ((lane >> 4) << 3)) * 72
                                  + kk*16 + ((lane >> 3) & 1) * 8;
                uint32_t rh[4];
                ldsm4(rh, stK + ro * 2);
                mma16816h(sc16[2*p],   qa_h[kk], rh[0], rh[1]);
                mma16816h(sc16[2*p+1], qa_h[kk], rh[2], rh[3]);
            }
        }

        uint32_t pa[8][4];
        __half2 acc0 = __floats2half2_rn(0.f, 0.f);
        __half2 acc1 = acc0;
        #pragma unroll
        for (int j = 0; j < 16; j++) {
            uint32_t e0 = ex2_f16x2(sc16[j][0]);
            uint32_t e1 = ex2_f16x2(sc16[j][1]);
            pa[j >> 1][(j & 1) * 2 + 0] = e0;
            pa[j >> 1][(j & 1) * 2 + 1] = e1;
            acc0 = __hadd2(acc0, *(__half2*)&e0);
            acc1 = __hadd2(acc1, *(__half2*)&e1);
        }
        {
            float2 f0 = __half22float2(acc0);
            float2 f1 = __half22float2(acc1);
            ol0 += f0.x + f0.y;
            ol1 += f1.x + f1.y;
        }

        #pragma unroll
        for (int kk2 = 0; kk2 < 8; kk2++) {
            #pragma unroll
            for (int p = 0; p < 4; p++) {
                const uint32_t ro = (kk2*16 + (lane & 7) + ((lane >> 3) & 1) * 8) * 72
                                  + p*16 + (lane >> 4) * 8;
                uint32_t rh[4];
                ldsm4t(rh, stV + ro * 2);
                mma16816(oacc[2*p],   pa[kk2], rh[0], rh[1]);
                mma16816(oacc[2*p+1], pa[kk2], rh[2], rh[3]);
            }
        }
    }

    ol0 += __shfl_xor_sync(0xffffffffu, ol0, 1);
    ol0 += __shfl_xor_sync(0xffffffffu, ol0, 2);
    ol1 += __shfl_xor_sync(0xffffffffu, ol1, 1);
    ol1 += __shfl_xor_sync(0xffffffffu, ol1, 2);

    const int b = bh >> 4;
    const float inv0 = 1.0f / ol0, inv1 = 1.0f / ol1;
    const int s0 = m0 + wm + (lane >> 2);
    #pragma unroll
    for (int di = 0; di < 8; di++) {
        const int d = di * 8 + (lane & 3) * 2;
        *(__half2*)&g_of[((size_t)(b * SS + s0)) * DD + h * HD + d] =
            __floats2half2_rn(oacc[di][0] * inv0, oacc[di][1] * inv0);
        *(__half2*)&g_of[((size_t)(b * SS + s0 + 8)) * DD + h * HD + d] =
            __floats2half2_rn(oacc[di][2] * inv1, oacc[di][3] * inv1);
    }
}

// ============================================================================
// Gating partial dots via HMMA, K-split 8-way: grid (32 m-tiles, 8 k-slices).
// Each CTA: 2 chunks of 64 K, writes fp32 partials to g_dotp[ky][row][24].
// 2-stage cp.async distance-1. Stage: A[128][72] + B[32][72] = 23040 B.
// ============================================================================
#define GT_STAGE_B 23040

__device__ __forceinline__ void gt_load_chunk(uint32_t st, int m0, int k0, int tid)
{
    #pragma unroll
    for (int sub = 0; sub < 4; sub++) {
        int id = tid + sub * 256;
        int r = id >> 3, j = id & 7;
        CP_ASYNC16(st + (r * 72 + j * 8) * 2, g_of + (size_t)(m0 + r) * DD + k0 + j * 8);
    }
    {
        int r = tid >> 3, j = tid & 7;
        CP_ASYNC16(st + (9216 + r * 72 + j * 8) * 2, g_wt + (size_t)r * DD + k0 + j * 8);
    }
}

__global__ void __launch_bounds__(256)
gating_part()
{
    extern __shared__ __half smdyn[];
    const uint32_t sb = smem_u32(smdyn);
    const int tid = threadIdx.x, lane = tid & 31, wid = tid >> 5;
    const int m0 = blockIdx.x * 128;
    const int ky = blockIdx.y;
    const int kb = ky * 128;
    const int wm = wid * 16;

    float c[3][4];
    #pragma unroll
    for (int i = 0; i < 3; i++)
        #pragma unroll
        for (int q = 0; q < 4; q++) c[i][q] = 0.0f;

    gt_load_chunk(sb, m0, kb, tid); CP_COMMIT();

    #pragma unroll
    for (int ch = 0; ch < 2; ch++) {
        CP_WAIT0();
        __syncthreads();
        if (ch + 1 < 2) {
            gt_load_chunk(sb + GT_STAGE_B, m0, kb + 64, tid);
            CP_COMMIT();
        }

        const uint32_t stA = sb + (ch & 1) * GT_STAGE_B;
        const uint32_t stB = stA + 18432;

        #pragma unroll
        for (int kk = 0; kk < 4; kk++) {
            uint32_t a4[4];
            ldsm4(a4, stA + ((wm + (lane & 15)) * 72 + kk * 16 + (lane >> 4) * 8) * 2);
            uint32_t b0[4];
            ldsm4(b0, stB + (((lane & 7) + ((lane >> 4) << 3)) * 72
                             + kk * 16 + ((lane >> 3) & 1) * 8) * 2);
            mma16816(c[0], a4, b0[0], b0[1]);
            mma16816(c[1], a4, b0[2], b0[3]);
            uint32_t b1[4];
            ldsm4(b1, stB + ((16 + (lane & 7) + ((lane >> 4) << 3)) * 72
                             + kk * 16 + ((lane >> 3) & 1) * 8) * 2);
            mma16816(c[2], a4, b1[0], b1[1]);
        }
    }

    #pragma unroll
    for (int ni = 0; ni < 3; ni++) {
        const int col = ni * 8 + (lane & 3) * 2;
        #pragma unroll
        for (int hf = 0; hf < 2; hf++) {
            const int row = m0 + wm + (lane >> 2) + hf * 8;
            float* dst = &g_dotp[((size_t)ky * MTOT + row) * 24 + col];
            dst[0] = c[ni][hf * 2 + 0];
            dst[1] = c[ni][hf * 2 + 1];
        }
    }
}

// ============================================================================
extern "C" void kernel_launch(void* const* d_in, const int* in_sizes, int n_in,
                              void* d_out, int out_size)
{
    const float* x     = (const float*)d_in[0];
    const float* Wq    = (const float*)d_in[1];
    const float* bq    = (const float*)d_in[2];
    const float* Wk    = (const float*)d_in[3];
    const float* bk    = (const float*)d_in[4];
    const float* Wv    = (const float*)d_in[5];
    const float* bv    = (const float*)d_in[6];
    const float* Wp    = (const float*)d_in[7];
    const float* bp    = (const float*)d_in[8];
    const float* Wr    = (const float*)d_in[9];
    const float* br    = (const float*)d_in[10];
    const float* Ws    = (const float*)d_in[11];
    const float* bs    = (const float*)d_in[12];
    const float* temp  = (const float*)d_in[13];
    const float* qe    = (const float*)d_in[14];
    float* out = (float*)d_out;

    static int attr_set = 0;
    if (!attr_set) {
        cudaFuncSetAttribute(dense_gemm, cudaFuncAttributeMaxDynamicSharedMemorySize,
                             3 * DG_STAGE_B);
        cudaFuncSetAttribute(attn, cudaFuncAttributeMaxDynamicSharedMemorySize,
                             2 * AT_STAGE_B);
        cudaFuncSetAttribute(gating_part, cudaFuncAttributeMaxDynamicSharedMemorySize,
                             2 * GT_STAGE_B);
        attr_set = 1;
    }

    split_all<<<dim3(1024, 1, 9), 256>>>(x, Wq, Wk, Wv, Wp, Wr, Ws);

    dense_gemm<<<dim3(8, 32, 3), 256, 3 * DG_STAGE_B>>>(0, bq, bk, bv, nullptr);
    attn<<<dim3(16, 32), 256, 2 * AT_STAGE_B>>>(temp, qe);
    gating_part<<<dim3(32, 8), 256, 2 * GT_STAGE_B>>>();
    dense_gemm<<<dim3(8, 32, 1), 256, 3 * DG_STAGE_B>>>(1, bp, br, bs, out);
}